// round 6
// baseline (speedup 1.0000x reference)
#include <cuda_runtime.h>
#include <stdint.h>

#define S_LEN   2048
#define BATCH   2
#define DMODEL  1024
#define NHEADS  16
#define DK      64
#define NTOK    (BATCH * S_LEN)      // 4096
#define QKV_N   (3 * DMODEL)         // 3072

// Scratch (allocation-free rule: __device__ globals)
__device__ float g_qkv[(size_t)NTOK * QKV_N];     // [token][3*D], tf32-rounded
__device__ float g_att[(size_t)NTOK * DMODEL];    // attn out, tf32-rounded
__device__ float g_in_r[(size_t)NTOK * DMODEL];   // rounded input
__device__ float g_wqkv_r[(size_t)DMODEL * QKV_N];
__device__ float g_wout_r[(size_t)DMODEL * DMODEL];

// ---------------------------------------------------------------------------
__device__ __forceinline__ uint32_t f2t(float x) {
    uint32_t r;
    asm("cvt.rna.tf32.f32 %0, %1;" : "=r"(r) : "f"(x));
    return r;
}
__device__ __forceinline__ float roundtf(float x) { return __uint_as_float(f2t(x)); }

__device__ __forceinline__ void mma8(float* c, const uint32_t* a, const uint32_t* b) {
    asm volatile(
        "mma.sync.aligned.m16n8k8.row.col.f32.tf32.tf32.f32 "
        "{%0,%1,%2,%3}, {%4,%5,%6,%7}, {%8,%9}, {%0,%1,%2,%3};"
        : "+f"(c[0]), "+f"(c[1]), "+f"(c[2]), "+f"(c[3])
        : "r"(a[0]), "r"(a[1]), "r"(a[2]), "r"(a[3]), "r"(b[0]), "r"(b[1]));
}

__device__ __forceinline__ void cp16(uint32_t saddr, const void* g) {
    asm volatile("cp.async.cg.shared.global [%0], [%1], 16;" :: "r"(saddr), "l"(g));
}
__device__ __forceinline__ void cp_commit() { asm volatile("cp.async.commit_group;"); }
__device__ __forceinline__ void cp_wait0()  { asm volatile("cp.async.wait_group 0;"); }
__device__ __forceinline__ void cp_wait1()  { asm volatile("cp.async.wait_group 1;"); }

// ---------------------------------------------------------------------------
// Pre-round: out[i] = tf32_rna(in[i])
// ---------------------------------------------------------------------------
__global__ void round_k(const float* __restrict__ in, float* __restrict__ out, int n4) {
    int i = blockIdx.x * blockDim.x + threadIdx.x;
    if (i < n4) {
        float4 v = ((const float4*)in)[i];
        v.x = roundtf(v.x); v.y = roundtf(v.y);
        v.z = roundtf(v.z); v.w = roundtf(v.w);
        ((float4*)out)[i] = v;
    }
}

// ---------------------------------------------------------------------------
// TF32 GEMM, inputs pre-rounded, 3-stage cp.async pipeline.
// C[M,N] = A[M,K]@B[K,N] (+bias); 128x128x32 tile, 256 thr, warp 32x64.
// Stage = As[128][36] + Bs[32][136] floats = 35840 B; 3 stages = 107520 B.
// ---------------------------------------------------------------------------
#define GSTG (128 * 36 + 32 * 136)          // floats per stage
#define GSMEM (3 * GSTG * (int)sizeof(float))

__global__ __launch_bounds__(256) void gemm_tf32_db(
    const float* __restrict__ A, const float* __restrict__ B,
    const float* __restrict__ bias, float* __restrict__ C,
    int M, int N, int K, int round_out)
{
    extern __shared__ float sg[];

    const int tid  = threadIdx.x;
    const int lane = tid & 31;
    const int wid  = tid >> 5;
    const int wm   = (wid & 3) * 32;
    const int wn   = (wid >> 2) * 64;
    const int g    = lane >> 2;
    const int q    = lane & 3;
    const int m0   = blockIdx.y * 128;
    const int n0   = blockIdx.x * 128;

    const uint32_t s0 = (uint32_t)__cvta_generic_to_shared(sg);

    float acc[2][8][4];
#pragma unroll
    for (int mt = 0; mt < 2; mt++)
#pragma unroll
        for (int nt = 0; nt < 8; nt++)
#pragma unroll
            for (int i = 0; i < 4; i++) acc[mt][nt][i] = 0.f;

    const int ar = tid >> 3, ac = (tid & 7) * 4;
    const int br = tid >> 5, bc = (tid & 31) * 4;

    auto prefetch = [&](int kt, int s) {
        const int k0 = kt * 32;
        const uint32_t sA = s0 + (uint32_t)(s * GSTG) * 4;
        const uint32_t sB = sA + 128 * 36 * 4;
#pragma unroll
        for (int i = 0; i < 4; i++) {
            int r = ar + i * 32;
            cp16(sA + (uint32_t)(r * 36 + ac) * 4, A + (size_t)(m0 + r) * K + k0 + ac);
        }
#pragma unroll
        for (int i = 0; i < 4; i++) {
            int r = br + i * 8;
            cp16(sB + (uint32_t)(r * 136 + bc) * 4, B + (size_t)(k0 + r) * N + n0 + bc);
        }
    };

    const int KT = K / 32;
    prefetch(0, 0); cp_commit();
    prefetch(1, 1); cp_commit();

    for (int kt = 0; kt < KT; kt++) {
        cp_wait1();                 // stage kt%3 resident (<=1 group pending)
        __syncthreads();
        if (kt + 2 < KT) { prefetch(kt + 2, (kt + 2) % 3); cp_commit(); }

        const float* Ab = sg + (kt % 3) * GSTG;
        const float* Bb = Ab + 128 * 36;
#pragma unroll
        for (int kk = 0; kk < 4; kk++) {
            uint32_t a[2][4], b[8][2];
#pragma unroll
            for (int mt = 0; mt < 2; mt++) {
                int r = wm + mt * 16 + g;
                a[mt][0] = __float_as_uint(Ab[r * 36 + kk * 8 + q]);
                a[mt][1] = __float_as_uint(Ab[(r + 8) * 36 + kk * 8 + q]);
                a[mt][2] = __float_as_uint(Ab[r * 36 + kk * 8 + q + 4]);
                a[mt][3] = __float_as_uint(Ab[(r + 8) * 36 + kk * 8 + q + 4]);
            }
#pragma unroll
            for (int nt = 0; nt < 8; nt++) {
                int c = wn + nt * 8 + g;
                b[nt][0] = __float_as_uint(Bb[(kk * 8 + q) * 136 + c]);
                b[nt][1] = __float_as_uint(Bb[(kk * 8 + q + 4) * 136 + c]);
            }
#pragma unroll
            for (int mt = 0; mt < 2; mt++)
#pragma unroll
                for (int nt = 0; nt < 8; nt++)
                    mma8(acc[mt][nt], a[mt], b[nt]);
        }
        __syncthreads();
    }

#pragma unroll
    for (int mt = 0; mt < 2; mt++) {
#pragma unroll
        for (int nt = 0; nt < 8; nt++) {
            int row = m0 + wm + mt * 16 + g;
            int col = n0 + wn + nt * 8 + 2 * q;
            float b0 = bias ? bias[col] : 0.f;
            float b1 = bias ? bias[col + 1] : 0.f;
            float v00 = acc[mt][nt][0] + b0, v01 = acc[mt][nt][1] + b1;
            float v10 = acc[mt][nt][2] + b0, v11 = acc[mt][nt][3] + b1;
            if (round_out) {
                v00 = roundtf(v00); v01 = roundtf(v01);
                v10 = roundtf(v10); v11 = roundtf(v11);
            }
            *(float2*)(C + (size_t)row * N + col)       = make_float2(v00, v01);
            *(float2*)(C + (size_t)(row + 8) * N + col) = make_float2(v10, v11);
        }
    }
}

// ---------------------------------------------------------------------------
// Flash attention, tf32 mma, q-tile 128 rows (256 thr, 8 warps x 16 rows),
// KV tile 64, cp.async double-buffered. Halves per-CTA-count KV traffic.
// Smem floats: Qs[128][68] + Ks[2][64][68] + Vs[2][64][72] + Ps[128][68]
//   = 35328 floats = 141312 B.
// ---------------------------------------------------------------------------
#define AQS 0
#define AKS (128 * 68)
#define AVS (AKS + 2 * 64 * 68)
#define APS (AVS + 2 * 64 * 72)
#define ASM_FLOATS (APS + 128 * 68)

__global__ __launch_bounds__(256) void attn_tf32_db(
    const float* __restrict__ qkv, float* __restrict__ out)
{
    extern __shared__ float sf[];
    float* Qs = sf + AQS;   // [128][68]
    float* Ks = sf + AKS;   // [2][64][68]
    float* Vs = sf + AVS;   // [2][64][72]
    float* Ps = sf + APS;   // [128][68]

    const int tid  = threadIdx.x;
    const int lane = tid & 31;
    const int wid  = tid >> 5;          // 0..7
    const int g    = lane >> 2;
    const int q    = lane & 3;
    const int wr   = wid * 16;          // warp's query-row origin (0..112)
    const int bh   = blockIdx.y;
    const int b    = bh >> 4;
    const int h    = bh & 15;
    const int q0   = blockIdx.x * 128;

    const float* Qg = qkv + (size_t)b * S_LEN * QKV_N + h * DK;
    const float* Kg = Qg + DMODEL;
    const float* Vg = Qg + 2 * DMODEL;

    const uint32_t sQ = (uint32_t)__cvta_generic_to_shared(Qs);
    const uint32_t sK = (uint32_t)__cvta_generic_to_shared(Ks);
    const uint32_t sV = (uint32_t)__cvta_generic_to_shared(Vs);

    const int lr = tid >> 4;            // 0..15
    const int lc = (tid & 15) * 4;      // float col 0..60

    // prologue: Q tile (128 rows) + KV tile 0 (64 rows)
#pragma unroll
    for (int i = 0; i < 8; i++) {
        int r = lr + i * 16;
        cp16(sQ + (uint32_t)(r * 68 + lc) * 4, Qg + (size_t)(q0 + r) * QKV_N + lc);
    }
#pragma unroll
    for (int i = 0; i < 4; i++) {
        int r = lr + i * 16;
        cp16(sK + (uint32_t)(r * 68 + lc) * 4, Kg + (size_t)r * QKV_N + lc);
        cp16(sV + (uint32_t)(r * 72 + lc) * 4, Vg + (size_t)r * QKV_N + lc);
    }
    cp_commit();

    float m_i[2] = {-1e30f, -1e30f};
    float l_i[2] = {0.f, 0.f};
    float o[8][4];
#pragma unroll
    for (int nt = 0; nt < 8; nt++)
#pragma unroll
        for (int i = 0; i < 4; i++) o[nt][i] = 0.f;

    const int NT = S_LEN / 64;
    for (int kt = 0; kt < NT; kt++) {
        cp_wait0();
        __syncthreads();
        if (kt + 1 < NT) {
            int buf = (kt + 1) & 1;
            const float* Kn = Kg + (size_t)(kt + 1) * 64 * QKV_N;
            const float* Vn = Vg + (size_t)(kt + 1) * 64 * QKV_N;
#pragma unroll
            for (int i = 0; i < 4; i++) {
                int r = lr + i * 16;
                cp16(sK + (uint32_t)((buf * 64 + r) * 68 + lc) * 4, Kn + (size_t)r * QKV_N + lc);
                cp16(sV + (uint32_t)((buf * 64 + r) * 72 + lc) * 4, Vn + (size_t)r * QKV_N + lc);
            }
            cp_commit();
        }
        const float* Kb = Ks + (kt & 1) * 64 * 68;
        const float* Vb = Vs + (kt & 1) * 64 * 72;

        // ---- S = Q K^T : warp computes 16x64 ----
        float sacc[8][4];
#pragma unroll
        for (int nt = 0; nt < 8; nt++)
#pragma unroll
            for (int i = 0; i < 4; i++) sacc[nt][i] = 0.f;

#pragma unroll
        for (int kk = 0; kk < 8; kk++) {
            uint32_t a[4], bf[2];
            int r = wr + g;
            a[0] = __float_as_uint(Qs[r * 68 + kk * 8 + q]);
            a[1] = __float_as_uint(Qs[(r + 8) * 68 + kk * 8 + q]);
            a[2] = __float_as_uint(Qs[r * 68 + kk * 8 + q + 4]);
            a[3] = __float_as_uint(Qs[(r + 8) * 68 + kk * 8 + q + 4]);
#pragma unroll
            for (int nt = 0; nt < 8; nt++) {
                bf[0] = __float_as_uint(Kb[(nt * 8 + g) * 68 + kk * 8 + q]);
                bf[1] = __float_as_uint(Kb[(nt * 8 + g) * 68 + kk * 8 + q + 4]);
                mma8(sacc[nt], a, bf);
            }
        }

        // ---- online softmax; true score = raw * 0.125 ----
#pragma unroll
        for (int rh = 0; rh < 2; rh++) {
            int row = wr + g + 8 * rh;
            float rm = -1e30f;
#pragma unroll
            for (int nt = 0; nt < 8; nt++)
                rm = fmaxf(rm, fmaxf(sacc[nt][2 * rh], sacc[nt][2 * rh + 1]));
            rm = fmaxf(rm, __shfl_xor_sync(0xffffffffu, rm, 1));
            rm = fmaxf(rm, __shfl_xor_sync(0xffffffffu, rm, 2));

            float mnew = fmaxf(m_i[rh], rm);
            float corr = __expf((m_i[rh] - mnew) * 0.125f);
            m_i[rh] = mnew;

            float rs = 0.f;
#pragma unroll
            for (int nt = 0; nt < 8; nt++) {
                float p0 = __expf((sacc[nt][2 * rh] - mnew) * 0.125f);
                float p1 = __expf((sacc[nt][2 * rh + 1] - mnew) * 0.125f);
                Ps[row * 68 + nt * 8 + 2 * q]     = roundtf(p0);
                Ps[row * 68 + nt * 8 + 2 * q + 1] = roundtf(p1);
                rs += p0 + p1;
            }
            rs += __shfl_xor_sync(0xffffffffu, rs, 1);
            rs += __shfl_xor_sync(0xffffffffu, rs, 2);
            l_i[rh] = l_i[rh] * corr + rs;
#pragma unroll
            for (int nt = 0; nt < 8; nt++) {
                o[nt][2 * rh]     *= corr;
                o[nt][2 * rh + 1] *= corr;
            }
        }
        __syncwarp();   // Ps rows are warp-private; warp-level visibility suffices

        // ---- O += P V ----
#pragma unroll
        for (int kk = 0; kk < 8; kk++) {
            uint32_t a[4], bf[2];
            int r = wr + g;
            a[0] = __float_as_uint(Ps[r * 68 + kk * 8 + q]);
            a[1] = __float_as_uint(Ps[(r + 8) * 68 + kk * 8 + q]);
            a[2] = __float_as_uint(Ps[r * 68 + kk * 8 + q + 4]);
            a[3] = __float_as_uint(Ps[(r + 8) * 68 + kk * 8 + q + 4]);
#pragma unroll
            for (int nt = 0; nt < 8; nt++) {
                bf[0] = __float_as_uint(Vb[(kk * 8 + q) * 72 + nt * 8 + g]);
                bf[1] = __float_as_uint(Vb[(kk * 8 + q + 4) * 72 + nt * 8 + g]);
                mma8(o[nt], a, bf);
            }
        }
    }

    // ---- normalize + write (tf32-rounded for GEMM2) ----
#pragma unroll
    for (int rh = 0; rh < 2; rh++) {
        float inv = 1.f / l_i[rh];
        int token = b * S_LEN + q0 + wr + g + 8 * rh;
        float* op = out + (size_t)token * DMODEL + h * DK;
#pragma unroll
        for (int nt = 0; nt < 8; nt++) {
            float2 v = make_float2(roundtf(o[nt][2 * rh] * inv),
                                   roundtf(o[nt][2 * rh + 1] * inv));
            *(float2*)(op + nt * 8 + 2 * q) = v;
        }
    }
}

// ---------------------------------------------------------------------------
extern "C" void kernel_launch(void* const* d_in, const int* in_sizes, int n_in,
                              void* d_out, int out_size)
{
    const float* input = (const float*)d_in[0];
    const float* W_qkv = (const float*)d_in[1];
    const float* b_qkv = (const float*)d_in[2];
    const float* W_out = (const float*)d_in[3];
    float* out = (float*)d_out;

    float *qkv_buf, *att_buf, *in_r, *wqkv_r, *wout_r;
    cudaGetSymbolAddress((void**)&qkv_buf, g_qkv);
    cudaGetSymbolAddress((void**)&att_buf, g_att);
    cudaGetSymbolAddress((void**)&in_r,   g_in_r);
    cudaGetSymbolAddress((void**)&wqkv_r, g_wqkv_r);
    cudaGetSymbolAddress((void**)&wout_r, g_wout_r);

    // 0) pre-round inputs/weights to tf32 grid
    {
        int n1 = NTOK * DMODEL / 4, n2 = DMODEL * QKV_N / 4, n3 = DMODEL * DMODEL / 4;
        round_k<<<(n1 + 255) / 256, 256>>>(input, in_r, n1);
        round_k<<<(n2 + 255) / 256, 256>>>(W_qkv, wqkv_r, n2);
        round_k<<<(n3 + 255) / 256, 256>>>(W_out, wout_r, n3);
    }

    cudaFuncSetAttribute(gemm_tf32_db,
                         cudaFuncAttributeMaxDynamicSharedMemorySize, GSMEM);

    // 1) QKV projection + bias (output tf32-rounded)
    gemm_tf32_db<<<dim3(QKV_N / 128, NTOK / 128), 256, GSMEM>>>(
        in_r, wqkv_r, b_qkv, qkv_buf, NTOK, QKV_N, DMODEL, 1);

    // 2) Flash attention (q-tile 128)
    const int asmem = ASM_FLOATS * (int)sizeof(float);   // 141312
    cudaFuncSetAttribute(attn_tf32_db,
                         cudaFuncAttributeMaxDynamicSharedMemorySize, asmem);
    attn_tf32_db<<<dim3(S_LEN / 128, BATCH * NHEADS), 256, asmem>>>(qkv_buf, att_buf);

    // 3) Output projection
    gemm_tf32_db<<<dim3(DMODEL / 128, NTOK / 128), 256, GSMEM>>>(
        att_buf, wout_r, nullptr, out, NTOK, DMODEL, DMODEL, 0);
}

// round 7
// speedup vs baseline: 1.0291x; 1.0291x over previous
#include <cuda_runtime.h>
#include <stdint.h>

#define S_LEN   2048
#define BATCH   2
#define DMODEL  1024
#define NHEADS  16
#define DK      64
#define NTOK    (BATCH * S_LEN)      // 4096
#define QKV_N   (3 * DMODEL)         // 3072

// Scratch (allocation-free rule: __device__ globals)
__device__ float g_qkv[(size_t)NTOK * QKV_N];       // [token][3*D], tf32-rounded
__device__ float g_att[(size_t)NTOK * DMODEL];      // attn out, tf32-rounded
__device__ float g_in_r[(size_t)NTOK * DMODEL];     // rounded input
__device__ float g_wqkvT[(size_t)QKV_N * DMODEL];   // W_qkv^T rounded [3072][1024]
__device__ float g_woutT[(size_t)DMODEL * DMODEL];  // W_out^T rounded [1024][1024]

// ---------------------------------------------------------------------------
__device__ __forceinline__ uint32_t f2t(float x) {
    uint32_t r;
    asm("cvt.rna.tf32.f32 %0, %1;" : "=r"(r) : "f"(x));
    return r;
}
__device__ __forceinline__ float roundtf(float x) { return __uint_as_float(f2t(x)); }

__device__ __forceinline__ void mma8(float* c, const uint32_t* a, const uint32_t* b) {
    asm volatile(
        "mma.sync.aligned.m16n8k8.row.col.f32.tf32.tf32.f32 "
        "{%0,%1,%2,%3}, {%4,%5,%6,%7}, {%8,%9}, {%0,%1,%2,%3};"
        : "+f"(c[0]), "+f"(c[1]), "+f"(c[2]), "+f"(c[3])
        : "r"(a[0]), "r"(a[1]), "r"(a[2]), "r"(a[3]), "r"(b[0]), "r"(b[1]));
}

// x4 ldmatrix of 8x8 b16 tiles == 8x4 tf32 quadrants
__device__ __forceinline__ void ldsm4(uint32_t* r, uint32_t addr) {
    asm volatile("ldmatrix.sync.aligned.m8n8.x4.shared.b16 {%0,%1,%2,%3}, [%4];"
                 : "=r"(r[0]), "=r"(r[1]), "=r"(r[2]), "=r"(r[3]) : "r"(addr));
}

__device__ __forceinline__ void cp16(uint32_t saddr, const void* g) {
    asm volatile("cp.async.cg.shared.global [%0], [%1], 16;" :: "r"(saddr), "l"(g));
}
__device__ __forceinline__ void cp_commit() { asm volatile("cp.async.commit_group;"); }
__device__ __forceinline__ void cp_wait0()  { asm volatile("cp.async.wait_group 0;"); }
__device__ __forceinline__ void cp_wait1()  { asm volatile("cp.async.wait_group 1;"); }

// ---------------------------------------------------------------------------
// Prep kernels
// ---------------------------------------------------------------------------
__global__ void round_k(const float* __restrict__ in, float* __restrict__ out, int n4) {
    int i = blockIdx.x * blockDim.x + threadIdx.x;
    if (i < n4) {
        float4 v = ((const float4*)in)[i];
        v.x = roundtf(v.x); v.y = roundtf(v.y);
        v.z = roundtf(v.z); v.w = roundtf(v.w);
        ((float4*)out)[i] = v;
    }
}

// out[C][R] = round(in[R][C])
__global__ void transpose_round_k(const float* __restrict__ in, float* __restrict__ out,
                                  int R, int C) {
    __shared__ float t[32][33];
    int c0 = blockIdx.x * 32, r0 = blockIdx.y * 32;
    int x = threadIdx.x, y = threadIdx.y;
#pragma unroll
    for (int j = 0; j < 4; j++)
        t[y + 8 * j][x] = in[(size_t)(r0 + y + 8 * j) * C + c0 + x];
    __syncthreads();
#pragma unroll
    for (int j = 0; j < 4; j++)
        out[(size_t)(c0 + y + 8 * j) * R + r0 + x] = roundtf(t[x][y + 8 * j]);
}

// ---------------------------------------------------------------------------
// TF32 GEMM via ldmatrix: C[M,N] = A[M,K] @ Bt[N,K]^T (+bias)
// Both operands k-major in smem [128][36] per stage; 3-stage cp.async.
// 256 thr = 8 warps (4x2), warp tile 32x64.
// Stage = 2*128*36 floats = 36864 B; 3 stages = 110592 B.
// ---------------------------------------------------------------------------
#define GSTG_F  (2 * 128 * 36)               // floats per stage
#define GSTG_B  (GSTG_F * 4)
#define GAB     (128 * 36 * 4)               // bytes: B tile offset in stage
#define GSMEM   (3 * GSTG_B)

__global__ __launch_bounds__(256) void gemm_tf32_ldsm(
    const float* __restrict__ A, const float* __restrict__ Bt,
    const float* __restrict__ bias, float* __restrict__ C,
    int M, int N, int K, int round_out)
{
    extern __shared__ float sg[];

    const int tid  = threadIdx.x;
    const int l    = tid & 31;
    const int wid  = tid >> 5;
    const int wm   = (wid & 3) * 32;
    const int wn   = (wid >> 2) * 64;
    const int g    = l >> 2;
    const int q    = l & 3;
    const int m0   = blockIdx.y * 128;
    const int n0   = blockIdx.x * 128;

    const uint32_t s0 = (uint32_t)__cvta_generic_to_shared(sg);

    float acc[2][8][4];
#pragma unroll
    for (int mt = 0; mt < 2; mt++)
#pragma unroll
        for (int nt = 0; nt < 8; nt++)
#pragma unroll
            for (int i = 0; i < 4; i++) acc[mt][nt][i] = 0.f;

    // ldmatrix per-lane byte offsets within a stage
    uint32_t aoff[2], boff[4];
#pragma unroll
    for (int mt = 0; mt < 2; mt++) {
        int row = wm + mt * 16 + ((l >> 3) & 1) * 8 + (l & 7);
        aoff[mt] = (uint32_t)(row * 36 + (l >> 4) * 4) * 4;
    }
#pragma unroll
    for (int j = 0; j < 4; j++) {
        int row = wn + 16 * j + (l >> 4) * 8 + (l & 7);
        boff[j] = GAB + (uint32_t)(row * 36 + ((l >> 3) & 1) * 4) * 4;
    }

    const int cr = tid >> 3, cc = (tid & 7) * 4;
    auto prefetch = [&](int kt, int s) {
        const int k0 = kt * 32;
        const uint32_t sA = s0 + (uint32_t)s * GSTG_B;
        const uint32_t sB = sA + GAB;
#pragma unroll
        for (int i = 0; i < 4; i++) {
            int r = cr + i * 32;
            cp16(sA + (uint32_t)(r * 36 + cc) * 4, A  + (size_t)(m0 + r) * K + k0 + cc);
            cp16(sB + (uint32_t)(r * 36 + cc) * 4, Bt + (size_t)(n0 + r) * K + k0 + cc);
        }
    };

    const int KT = K / 32;
    prefetch(0, 0); cp_commit();
    prefetch(1, 1); cp_commit();

    for (int kt = 0; kt < KT; kt++) {
        cp_wait1();
        __syncthreads();
        if (kt + 2 < KT) { prefetch(kt + 2, (kt + 2) % 3); cp_commit(); }

        const uint32_t sb = s0 + (uint32_t)(kt % 3) * GSTG_B;
#pragma unroll
        for (int kk = 0; kk < 4; kk++) {
            uint32_t a[2][4], b[4][4];
#pragma unroll
            for (int mt = 0; mt < 2; mt++) ldsm4(a[mt], sb + aoff[mt] + kk * 32);
#pragma unroll
            for (int j = 0; j < 4; j++)   ldsm4(b[j], sb + boff[j] + kk * 32);
#pragma unroll
            for (int mt = 0; mt < 2; mt++)
#pragma unroll
                for (int nt = 0; nt < 8; nt++)
                    mma8(acc[mt][nt], a[mt], &b[nt >> 1][(nt & 1) * 2]);
        }
        __syncthreads();
    }

#pragma unroll
    for (int mt = 0; mt < 2; mt++) {
#pragma unroll
        for (int nt = 0; nt < 8; nt++) {
            int row = m0 + wm + mt * 16 + g;
            int col = n0 + wn + nt * 8 + 2 * q;
            float b0 = bias ? bias[col] : 0.f;
            float b1 = bias ? bias[col + 1] : 0.f;
            float v00 = acc[mt][nt][0] + b0, v01 = acc[mt][nt][1] + b1;
            float v10 = acc[mt][nt][2] + b0, v11 = acc[mt][nt][3] + b1;
            if (round_out) {
                v00 = roundtf(v00); v01 = roundtf(v01);
                v10 = roundtf(v10); v11 = roundtf(v11);
            }
            *(float2*)(C + (size_t)row * N + col)       = make_float2(v00, v01);
            *(float2*)(C + (size_t)(row + 8) * N + col) = make_float2(v10, v11);
        }
    }
}

// ---------------------------------------------------------------------------
// Flash attention: tf32 mma + ldmatrix for Q/K/P frags, cp.async dbuf K/V.
// R3 shape: q-tile 64, 128 thr = 4 warps x 16 rows (2 CTA/SM).
// Smem floats: Qs[64][68] + Ks[2][64][68] + Vs[2][64][72] + Ps[64][68]
//   = 26624 floats = 106496 B.
// ---------------------------------------------------------------------------
#define AQS 0
#define AKS (64 * 68)
#define AVS (AKS + 2 * 64 * 68)
#define APS (AVS + 2 * 64 * 72)
#define ASM_FLOATS (APS + 64 * 68)

__global__ __launch_bounds__(128) void attn_tf32_ldsm(
    const float* __restrict__ qkv, float* __restrict__ out)
{
    extern __shared__ float sf[];
    float* Qs = sf + AQS;
    float* Ks = sf + AKS;
    float* Vs = sf + AVS;
    float* Ps = sf + APS;

    const int tid  = threadIdx.x;
    const int l    = tid & 31;
    const int wid  = tid >> 5;
    const int g    = l >> 2;
    const int q    = l & 3;
    const int wr   = wid * 16;
    const int bh   = blockIdx.y;
    const int b    = bh >> 4;
    const int h    = bh & 15;
    const int q0   = blockIdx.x * 64;

    const float* Qg = qkv + (size_t)b * S_LEN * QKV_N + h * DK;
    const float* Kg = Qg + DMODEL;
    const float* Vg = Qg + 2 * DMODEL;

    const uint32_t sQ = (uint32_t)__cvta_generic_to_shared(Qs);
    const uint32_t sK = (uint32_t)__cvta_generic_to_shared(Ks);
    const uint32_t sV = (uint32_t)__cvta_generic_to_shared(Vs);
    const uint32_t sP = (uint32_t)__cvta_generic_to_shared(Ps);

    // ldmatrix per-lane offsets (stride 68 floats)
    const uint32_t qoff = (uint32_t)((wr + ((l >> 3) & 1) * 8 + (l & 7)) * 68
                                     + (l >> 4) * 4) * 4;      // A-frag in Qs/Ps
    uint32_t koff[4];
#pragma unroll
    for (int j = 0; j < 4; j++) {
        int row = 16 * j + (l >> 4) * 8 + (l & 7);
        koff[j] = (uint32_t)(row * 68 + ((l >> 3) & 1) * 4) * 4; // B-frag in Ks
    }

    const int lr = tid >> 4, lc = (tid & 15) * 4;

    // prologue: Q tile + KV tile 0
#pragma unroll
    for (int i = 0; i < 8; i++) {
        int r = lr + i * 8;
        cp16(sQ + (uint32_t)(r * 68 + lc) * 4, Qg + (size_t)(q0 + r) * QKV_N + lc);
    }
#pragma unroll
    for (int i = 0; i < 8; i++) {
        int r = lr + i * 8;
        cp16(sK + (uint32_t)(r * 68 + lc) * 4, Kg + (size_t)r * QKV_N + lc);
        cp16(sV + (uint32_t)(r * 72 + lc) * 4, Vg + (size_t)r * QKV_N + lc);
    }
    cp_commit();

    float m_i[2] = {-1e30f, -1e30f};
    float l_i[2] = {0.f, 0.f};
    float o[8][4];
#pragma unroll
    for (int nt = 0; nt < 8; nt++)
#pragma unroll
        for (int i = 0; i < 4; i++) o[nt][i] = 0.f;

    const int NT = S_LEN / 64;
    for (int kt = 0; kt < NT; kt++) {
        cp_wait0();
        __syncthreads();
        if (kt + 1 < NT) {
            int buf = (kt + 1) & 1;
            const float* Kn = Kg + (size_t)(kt + 1) * 64 * QKV_N;
            const float* Vn = Vg + (size_t)(kt + 1) * 64 * QKV_N;
#pragma unroll
            for (int i = 0; i < 8; i++) {
                int r = lr + i * 8;
                cp16(sK + (uint32_t)((buf * 64 + r) * 68 + lc) * 4, Kn + (size_t)r * QKV_N + lc);
                cp16(sV + (uint32_t)((buf * 64 + r) * 72 + lc) * 4, Vn + (size_t)r * QKV_N + lc);
            }
            cp_commit();
        }
        const uint32_t sKb = sK + (uint32_t)(kt & 1) * 64 * 68 * 4;
        const float* Vb = Vs + (kt & 1) * 64 * 72;

        // ---- S = Q K^T ----
        float sacc[8][4];
#pragma unroll
        for (int nt = 0; nt < 8; nt++)
#pragma unroll
            for (int i = 0; i < 4; i++) sacc[nt][i] = 0.f;

#pragma unroll
        for (int kk = 0; kk < 8; kk++) {
            uint32_t a[4], kb[4][4];
            ldsm4(a, sQ + qoff + kk * 32);
#pragma unroll
            for (int j = 0; j < 4; j++) ldsm4(kb[j], sKb + koff[j] + kk * 32);
#pragma unroll
            for (int nt = 0; nt < 8; nt++)
                mma8(sacc[nt], a, &kb[nt >> 1][(nt & 1) * 2]);
        }

        // ---- online softmax; true score = raw * 0.125 ----
#pragma unroll
        for (int rh = 0; rh < 2; rh++) {
            int row = wr + g + 8 * rh;
            float rm = -1e30f;
#pragma unroll
            for (int nt = 0; nt < 8; nt++)
                rm = fmaxf(rm, fmaxf(sacc[nt][2 * rh], sacc[nt][2 * rh + 1]));
            rm = fmaxf(rm, __shfl_xor_sync(0xffffffffu, rm, 1));
            rm = fmaxf(rm, __shfl_xor_sync(0xffffffffu, rm, 2));

            float mnew = fmaxf(m_i[rh], rm);
            float corr = __expf((m_i[rh] - mnew) * 0.125f);
            m_i[rh] = mnew;

            float rs = 0.f;
#pragma unroll
            for (int nt = 0; nt < 8; nt++) {
                float p0 = __expf((sacc[nt][2 * rh] - mnew) * 0.125f);
                float p1 = __expf((sacc[nt][2 * rh + 1] - mnew) * 0.125f);
                Ps[row * 68 + nt * 8 + 2 * q]     = roundtf(p0);
                Ps[row * 68 + nt * 8 + 2 * q + 1] = roundtf(p1);
                rs += p0 + p1;
            }
            rs += __shfl_xor_sync(0xffffffffu, rs, 1);
            rs += __shfl_xor_sync(0xffffffffu, rs, 2);
            l_i[rh] = l_i[rh] * corr + rs;
#pragma unroll
            for (int nt = 0; nt < 8; nt++) {
                o[nt][2 * rh]     *= corr;
                o[nt][2 * rh + 1] *= corr;
            }
        }
        __syncwarp();   // Ps rows warp-private

        // ---- O += P V ----
#pragma unroll
        for (int kk = 0; kk < 8; kk++) {
            uint32_t a[4], bf[2];
            ldsm4(a, sP + qoff + kk * 32);
#pragma unroll
            for (int nt = 0; nt < 8; nt++) {
                bf[0] = __float_as_uint(Vb[(kk * 8 + q) * 72 + nt * 8 + g]);
                bf[1] = __float_as_uint(Vb[(kk * 8 + q + 4) * 72 + nt * 8 + g]);
                mma8(o[nt], a, bf);
            }
        }
    }

    // ---- normalize + write (tf32-rounded for GEMM2) ----
#pragma unroll
    for (int rh = 0; rh < 2; rh++) {
        float inv = 1.f / l_i[rh];
        int token = b * S_LEN + q0 + wr + g + 8 * rh;
        float* op = out + (size_t)token * DMODEL + h * DK;
#pragma unroll
        for (int nt = 0; nt < 8; nt++) {
            float2 v = make_float2(roundtf(o[nt][2 * rh] * inv),
                                   roundtf(o[nt][2 * rh + 1] * inv));
            *(float2*)(op + nt * 8 + 2 * q) = v;
        }
    }
}

// ---------------------------------------------------------------------------
extern "C" void kernel_launch(void* const* d_in, const int* in_sizes, int n_in,
                              void* d_out, int out_size)
{
    const float* input = (const float*)d_in[0];
    const float* W_qkv = (const float*)d_in[1];
    const float* b_qkv = (const float*)d_in[2];
    const float* W_out = (const float*)d_in[3];
    float* out = (float*)d_out;

    float *qkv_buf, *att_buf, *in_r, *wqkvT, *woutT;
    cudaGetSymbolAddress((void**)&qkv_buf, g_qkv);
    cudaGetSymbolAddress((void**)&att_buf, g_att);
    cudaGetSymbolAddress((void**)&in_r,   g_in_r);
    cudaGetSymbolAddress((void**)&wqkvT,  g_wqkvT);
    cudaGetSymbolAddress((void**)&woutT,  g_woutT);

    // 0) round input; transpose+round weights (k-major B operands)
    {
        int n1 = NTOK * DMODEL / 4;
        round_k<<<(n1 + 255) / 256, 256>>>(input, in_r, n1);
        transpose_round_k<<<dim3(QKV_N / 32, DMODEL / 32), dim3(32, 8)>>>(
            W_qkv, wqkvT, DMODEL, QKV_N);
        transpose_round_k<<<dim3(DMODEL / 32, DMODEL / 32), dim3(32, 8)>>>(
            W_out, woutT, DMODEL, DMODEL);
    }

    cudaFuncSetAttribute(gemm_tf32_ldsm,
                         cudaFuncAttributeMaxDynamicSharedMemorySize, GSMEM);

    // 1) QKV projection + bias (output tf32-rounded)
    gemm_tf32_ldsm<<<dim3(QKV_N / 128, NTOK / 128), 256, GSMEM>>>(
        in_r, wqkvT, b_qkv, qkv_buf, NTOK, QKV_N, DMODEL, 1);

    // 2) Flash attention (q-tile 64, ldmatrix frags)
    const int asmem = ASM_FLOATS * (int)sizeof(float);   // 106496
    cudaFuncSetAttribute(attn_tf32_ldsm,
                         cudaFuncAttributeMaxDynamicSharedMemorySize, asmem);
    attn_tf32_ldsm<<<dim3(S_LEN / 64, BATCH * NHEADS), 128, asmem>>>(qkv_buf, att_buf);

    // 3) Output projection
    gemm_tf32_ldsm<<<dim3(DMODEL / 128, NTOK / 128), 256, GSMEM>>>(
        att_buf, woutT, nullptr, out, NTOK, DMODEL, DMODEL, 0);
}

// round 8
// speedup vs baseline: 1.8664x; 1.8136x over previous
#include <cuda_runtime.h>
#include <cuda_fp16.h>
#include <stdint.h>

#define S_LEN   2048
#define BATCH   2
#define DMODEL  1024
#define NHEADS  16
#define DK      64
#define NTOK    (BATCH * S_LEN)      // 4096
#define QKV_N   (3 * DMODEL)         // 3072

// Scratch (allocation-free rule: __device__ globals)
__device__ __half g_in_h[(size_t)NTOK * DMODEL];     // input, fp16
__device__ __half g_wqkvT[(size_t)QKV_N * DMODEL];   // W_qkv^T fp16 [3072][1024]
__device__ __half g_woutT[(size_t)DMODEL * DMODEL];  // W_out^T fp16
__device__ __half g_qkv[(size_t)NTOK * QKV_N];       // qkv, fp16
__device__ __half g_att[(size_t)NTOK * DMODEL];      // attn out, fp16

// ---------------------------------------------------------------------------
__device__ __forceinline__ void mma16(float* c, const uint32_t* a, const uint32_t* b) {
    asm volatile(
        "mma.sync.aligned.m16n8k16.row.col.f32.f16.f16.f32 "
        "{%0,%1,%2,%3}, {%4,%5,%6,%7}, {%8,%9}, {%0,%1,%2,%3};"
        : "+f"(c[0]), "+f"(c[1]), "+f"(c[2]), "+f"(c[3])
        : "r"(a[0]), "r"(a[1]), "r"(a[2]), "r"(a[3]), "r"(b[0]), "r"(b[1]));
}
__device__ __forceinline__ void ldsm4(uint32_t* r, uint32_t addr) {
    asm volatile("ldmatrix.sync.aligned.m8n8.x4.shared.b16 {%0,%1,%2,%3}, [%4];"
                 : "=r"(r[0]), "=r"(r[1]), "=r"(r[2]), "=r"(r[3]) : "r"(addr));
}
__device__ __forceinline__ void ldsm4t(uint32_t* r, uint32_t addr) {
    asm volatile("ldmatrix.sync.aligned.m8n8.x4.trans.shared.b16 {%0,%1,%2,%3}, [%4];"
                 : "=r"(r[0]), "=r"(r[1]), "=r"(r[2]), "=r"(r[3]) : "r"(addr));
}
__device__ __forceinline__ void cp16(uint32_t saddr, const void* g) {
    asm volatile("cp.async.cg.shared.global [%0], [%1], 16;" :: "r"(saddr), "l"(g));
}
__device__ __forceinline__ void cp_commit() { asm volatile("cp.async.commit_group;"); }
__device__ __forceinline__ void cp_wait0()  { asm volatile("cp.async.wait_group 0;"); }
__device__ __forceinline__ void cp_wait1()  { asm volatile("cp.async.wait_group 1;"); }

// ---------------------------------------------------------------------------
// Prep: f32 -> f16; transpose f32 -> f16
// ---------------------------------------------------------------------------
__global__ void tohalf_k(const float* __restrict__ in, __half* __restrict__ out, int n4) {
    int i = blockIdx.x * blockDim.x + threadIdx.x;
    if (i < n4) {
        float4 v = ((const float4*)in)[i];
        __half2 h0 = __floats2half2_rn(v.x, v.y);
        __half2 h1 = __floats2half2_rn(v.z, v.w);
        ((uint2*)out)[i] = make_uint2(*(uint32_t*)&h0, *(uint32_t*)&h1);
    }
}

// out[C][R] = half(in[R][C])
__global__ void transpose_h(const float* __restrict__ in, __half* __restrict__ out,
                            int R, int C) {
    __shared__ float t[32][33];
    int c0 = blockIdx.x * 32, r0 = blockIdx.y * 32;
    int x = threadIdx.x, y = threadIdx.y;
#pragma unroll
    for (int j = 0; j < 4; j++)
        t[y + 8 * j][x] = in[(size_t)(r0 + y + 8 * j) * C + c0 + x];
    __syncthreads();
#pragma unroll
    for (int j = 0; j < 4; j++)
        out[(size_t)(c0 + y + 8 * j) * R + r0 + x] = __float2half_rn(t[x][y + 8 * j]);
}

// ---------------------------------------------------------------------------
// FP16 GEMM (fp32 acc): C[M,N] = A[M,K] @ Bt[N,K]^T (+bias)
// 128x128 tile, BK=32 halves, 3-stage cp.async, 256 thr, warp 32x64.
// Smem stage: As[128][40]h + Bs[128][40]h = 20480 B; 3 stages = 61440 B.
// ---------------------------------------------------------------------------
#define GKS    40                       // smem stride in halves
#define GAB    (128 * GKS * 2)          // A tile bytes (10240)
#define GSTG_B (2 * GAB)                // stage bytes (20480)
#define GSMEM  (3 * GSTG_B)

__global__ __launch_bounds__(256) void gemm_h(
    const __half* __restrict__ A, const __half* __restrict__ Bt,
    const float* __restrict__ bias, __half* __restrict__ Ch,
    float* __restrict__ Cf, int M, int N, int K)
{
    extern __shared__ char sg[];

    const int tid  = threadIdx.x;
    const int l    = tid & 31;
    const int wid  = tid >> 5;
    const int wm   = (wid & 3) * 32;
    const int wn   = (wid >> 2) * 64;
    const int g    = l >> 2;
    const int q    = l & 3;
    const int m0   = blockIdx.y * 128;
    const int n0   = blockIdx.x * 128;

    const uint32_t s0 = (uint32_t)__cvta_generic_to_shared(sg);

    float acc[2][8][4];
#pragma unroll
    for (int mt = 0; mt < 2; mt++)
#pragma unroll
        for (int nt = 0; nt < 8; nt++)
#pragma unroll
            for (int i = 0; i < 4; i++) acc[mt][nt][i] = 0.f;

    // ldmatrix per-lane byte offsets within a stage
    uint32_t aoff[2], boff[4];
#pragma unroll
    for (int mt = 0; mt < 2; mt++) {
        int row = wm + mt * 16 + ((l >> 3) & 1) * 8 + (l & 7);
        aoff[mt] = (uint32_t)(row * GKS + (l >> 4) * 8) * 2;
    }
#pragma unroll
    for (int j = 0; j < 4; j++) {
        int row = wn + 16 * j + (l & 7) + (l >> 4) * 8;
        boff[j] = GAB + (uint32_t)(row * GKS + ((l >> 3) & 1) * 8) * 2;
    }

    // cp.async coords: 2 chunks/thread/tile
    const int cr = tid >> 1;              // row 0..127
    const int cb = (tid & 1) * 32;        // byte col {0,32}
    auto prefetch = [&](int kt, int s) {
        const int k0 = kt * 32;           // halves
        const uint32_t sA = s0 + (uint32_t)s * GSTG_B;
        const uint32_t sB = sA + GAB;
        const __half* Ag = A  + (size_t)(m0 + cr) * K + k0 + (cb >> 1);
        const __half* Bg = Bt + (size_t)(n0 + cr) * K + k0 + (cb >> 1);
        uint32_t so = (uint32_t)(cr * GKS) * 2 + cb;
        cp16(sA + so,      Ag);
        cp16(sA + so + 16, Ag + 8);
        cp16(sB + so,      Bg);
        cp16(sB + so + 16, Bg + 8);
    };

    const int KT = K / 32;
    prefetch(0, 0); cp_commit();
    prefetch(1, 1); cp_commit();

    for (int kt = 0; kt < KT; kt++) {
        cp_wait1();
        __syncthreads();
        if (kt + 2 < KT) { prefetch(kt + 2, (kt + 2) % 3); cp_commit(); }

        const uint32_t sb = s0 + (uint32_t)(kt % 3) * GSTG_B;
#pragma unroll
        for (int kk = 0; kk < 2; kk++) {      // k16 steps
            uint32_t a[2][4], b[4][4];
#pragma unroll
            for (int mt = 0; mt < 2; mt++) ldsm4(a[mt], sb + aoff[mt] + kk * 32);
#pragma unroll
            for (int j = 0; j < 4; j++)   ldsm4(b[j], sb + boff[j] + kk * 32);
#pragma unroll
            for (int mt = 0; mt < 2; mt++)
#pragma unroll
                for (int nt = 0; nt < 8; nt++)
                    mma16(acc[mt][nt], a[mt], &b[nt >> 1][(nt & 1) * 2]);
        }
        __syncthreads();
    }

#pragma unroll
    for (int mt = 0; mt < 2; mt++) {
#pragma unroll
        for (int nt = 0; nt < 8; nt++) {
            int row = m0 + wm + mt * 16 + g;
            int col = n0 + wn + nt * 8 + 2 * q;
            float b0 = bias ? bias[col] : 0.f;
            float b1 = bias ? bias[col + 1] : 0.f;
            float v00 = acc[mt][nt][0] + b0, v01 = acc[mt][nt][1] + b1;
            float v10 = acc[mt][nt][2] + b0, v11 = acc[mt][nt][3] + b1;
            if (Ch) {
                *(__half2*)(Ch + (size_t)row * N + col)       = __floats2half2_rn(v00, v01);
                *(__half2*)(Ch + (size_t)(row + 8) * N + col) = __floats2half2_rn(v10, v11);
            } else {
                *(float2*)(Cf + (size_t)row * N + col)       = make_float2(v00, v01);
                *(float2*)(Cf + (size_t)(row + 8) * N + col) = make_float2(v10, v11);
            }
        }
    }
}

// ---------------------------------------------------------------------------
// FP16 flash attention: q-tile 64, 128 thr = 4 warps x 16 rows.
// QK^T and PV on m16n8k16; V B-frags via ldmatrix.trans (no scalar LDS).
// Smem halves (stride 72): Qs[64] + Ks[2][64] + Vs[2][64] + Ps[64]
//   = 6*64*72*2 = 55296 B  -> up to 4 CTAs/SM.
// ---------------------------------------------------------------------------
#define AST 72                          // stride in halves
#define ATB (64 * AST * 2)              // one 64-row tile bytes (9216)
#define AQS_B 0
#define AKS_B ATB
#define AVS_B (AKS_B + 2 * ATB)
#define APS_B (AVS_B + 2 * ATB)
#define ASMEM (APS_B + ATB)

__global__ __launch_bounds__(128) void attn_h(
    const __half* __restrict__ qkv, __half* __restrict__ out)
{
    extern __shared__ char sc[];
    const uint32_t s0 = (uint32_t)__cvta_generic_to_shared(sc);
    const uint32_t sQ = s0 + AQS_B;
    const uint32_t sK = s0 + AKS_B;
    const uint32_t sV = s0 + AVS_B;
    const uint32_t sP = s0 + APS_B;
    __half* Ps = (__half*)(sc + APS_B);

    const int tid  = threadIdx.x;
    const int l    = tid & 31;
    const int wid  = tid >> 5;
    const int g    = l >> 2;
    const int q    = l & 3;
    const int wr   = wid * 16;
    const int bh   = blockIdx.y;
    const int b    = bh >> 4;
    const int h    = bh & 15;
    const int q0   = blockIdx.x * 64;

    const __half* Qg = qkv + (size_t)b * S_LEN * QKV_N + h * DK;
    const __half* Kg = Qg + DMODEL;
    const __half* Vg = Qg + 2 * DMODEL;

    // ldmatrix per-lane byte offsets
    const uint32_t afr = (uint32_t)((wr + ((l >> 3) & 1) * 8 + (l & 7)) * AST
                                    + (l >> 4) * 8) * 2;        // A-frag (Qs/Ps)
    uint32_t koff[4], voff[4];
#pragma unroll
    for (int j = 0; j < 4; j++) {
        int krow = 16 * j + (l & 7) + (l >> 4) * 8;             // n=kv row
        koff[j] = (uint32_t)(krow * AST + ((l >> 3) & 1) * 8) * 2;
        int vrow = (l & 7) + ((l >> 3) & 1) * 8;                // k=kv row
        int vcol = 16 * j + (l >> 4) * 8;                       // n=d col
        voff[j] = (uint32_t)(vrow * AST + vcol) * 2;
    }

    // cp.async coords: row=tid>>3 (+16/pass), chunk=(tid&7)*8 halves
    const int lr = tid >> 3;
    const int lch = (tid & 7) * 8;
    auto load_tile = [&](uint32_t sdst, const __half* gsrc) {
#pragma unroll
        for (int i = 0; i < 4; i++) {
            int r = lr + i * 16;
            cp16(sdst + (uint32_t)(r * AST + lch) * 2, gsrc + (size_t)r * QKV_N + lch);
        }
    };

    // prologue: Q + KV tile 0
    load_tile(sQ, Qg + (size_t)q0 * QKV_N);
    load_tile(sK, Kg);
    load_tile(sV, Vg);
    cp_commit();

    float m_i[2] = {-1e30f, -1e30f};
    float l_i[2] = {0.f, 0.f};
    float o[8][4];
#pragma unroll
    for (int nt = 0; nt < 8; nt++)
#pragma unroll
        for (int i = 0; i < 4; i++) o[nt][i] = 0.f;

    const int NT = S_LEN / 64;
    for (int kt = 0; kt < NT; kt++) {
        cp_wait0();
        __syncthreads();
        if (kt + 1 < NT) {
            uint32_t buf = (uint32_t)((kt + 1) & 1) * ATB;
            load_tile(sK + buf, Kg + (size_t)(kt + 1) * 64 * QKV_N);
            load_tile(sV + buf, Vg + (size_t)(kt + 1) * 64 * QKV_N);
            cp_commit();
        }
        const uint32_t sKb = sK + (uint32_t)(kt & 1) * ATB;
        const uint32_t sVb = sV + (uint32_t)(kt & 1) * ATB;

        // ---- S = Q K^T ----
        float sacc[8][4];
#pragma unroll
        for (int nt = 0; nt < 8; nt++)
#pragma unroll
            for (int i = 0; i < 4; i++) sacc[nt][i] = 0.f;

#pragma unroll
        for (int kk = 0; kk < 4; kk++) {          // DK=64 -> 4 k16 steps
            uint32_t a[4], kb[4][4];
            ldsm4(a, sQ + afr + kk * 32);
#pragma unroll
            for (int j = 0; j < 4; j++) ldsm4(kb[j], sKb + koff[j] + kk * 32);
#pragma unroll
            for (int nt = 0; nt < 8; nt++)
                mma16(sacc[nt], a, &kb[nt >> 1][(nt & 1) * 2]);
        }

        // ---- online softmax; true score = raw * 0.125 ----
#pragma unroll
        for (int rh = 0; rh < 2; rh++) {
            int row = wr + g + 8 * rh;
            float rm = -1e30f;
#pragma unroll
            for (int nt = 0; nt < 8; nt++)
                rm = fmaxf(rm, fmaxf(sacc[nt][2 * rh], sacc[nt][2 * rh + 1]));
            rm = fmaxf(rm, __shfl_xor_sync(0xffffffffu, rm, 1));
            rm = fmaxf(rm, __shfl_xor_sync(0xffffffffu, rm, 2));

            float mnew = fmaxf(m_i[rh], rm);
            float corr = __expf((m_i[rh] - mnew) * 0.125f);
            m_i[rh] = mnew;

            float rs = 0.f;
#pragma unroll
            for (int nt = 0; nt < 8; nt++) {
                float p0 = __expf((sacc[nt][2 * rh] - mnew) * 0.125f);
                float p1 = __expf((sacc[nt][2 * rh + 1] - mnew) * 0.125f);
                *(__half2*)(Ps + row * AST + nt * 8 + 2 * q) = __floats2half2_rn(p0, p1);
                rs += p0 + p1;
            }
            rs += __shfl_xor_sync(0xffffffffu, rs, 1);
            rs += __shfl_xor_sync(0xffffffffu, rs, 2);
            l_i[rh] = l_i[rh] * corr + rs;
#pragma unroll
            for (int nt = 0; nt < 8; nt++) {
                o[nt][2 * rh]     *= corr;
                o[nt][2 * rh + 1] *= corr;
            }
        }
        __syncwarp();   // Ps rows warp-private

        // ---- O += P V (V via ldmatrix.trans) ----
#pragma unroll
        for (int kk = 0; kk < 4; kk++) {          // kv 64 -> 4 k16 steps
            uint32_t a[4], vb[4][4];
            ldsm4(a, sP + afr + kk * 32);
            const uint32_t vkk = sVb + (uint32_t)(kk * 16 * AST) * 2;
#pragma unroll
            for (int j = 0; j < 4; j++) ldsm4t(vb[j], vkk + voff[j]);
#pragma unroll
            for (int nt = 0; nt < 8; nt++)
                mma16(o[nt], a, &vb[nt >> 1][(nt & 1) * 2]);
        }
    }

    // ---- normalize + write fp16 ----
#pragma unroll
    for (int rh = 0; rh < 2; rh++) {
        float inv = 1.f / l_i[rh];
        int token = b * S_LEN + q0 + wr + g + 8 * rh;
        __half* op = out + (size_t)token * DMODEL + h * DK;
#pragma unroll
        for (int nt = 0; nt < 8; nt++)
            *(__half2*)(op + nt * 8 + 2 * q) =
                __floats2half2_rn(o[nt][2 * rh] * inv, o[nt][2 * rh + 1] * inv);
    }
}

// ---------------------------------------------------------------------------
extern "C" void kernel_launch(void* const* d_in, const int* in_sizes, int n_in,
                              void* d_out, int out_size)
{
    const float* input = (const float*)d_in[0];
    const float* W_qkv = (const float*)d_in[1];
    const float* b_qkv = (const float*)d_in[2];
    const float* W_out = (const float*)d_in[3];
    float* out = (float*)d_out;

    __half *in_h, *wqkvT, *woutT, *qkv_buf, *att_buf;
    cudaGetSymbolAddress((void**)&in_h,    g_in_h);
    cudaGetSymbolAddress((void**)&wqkvT,   g_wqkvT);
    cudaGetSymbolAddress((void**)&woutT,   g_woutT);
    cudaGetSymbolAddress((void**)&qkv_buf, g_qkv);
    cudaGetSymbolAddress((void**)&att_buf, g_att);

    // 0) input -> fp16; weights -> fp16 transposed (k-major B operands)
    {
        int n1 = NTOK * DMODEL / 4;
        tohalf_k<<<(n1 + 255) / 256, 256>>>(input, in_h, n1);
        transpose_h<<<dim3(QKV_N / 32, DMODEL / 32), dim3(32, 8)>>>(
            W_qkv, wqkvT, DMODEL, QKV_N);
        transpose_h<<<dim3(DMODEL / 32, DMODEL / 32), dim3(32, 8)>>>(
            W_out, woutT, DMODEL, DMODEL);
    }

    cudaFuncSetAttribute(gemm_h, cudaFuncAttributeMaxDynamicSharedMemorySize, GSMEM);

    // 1) QKV projection + bias -> fp16 qkv
    gemm_h<<<dim3(QKV_N / 128, NTOK / 128), 256, GSMEM>>>(
        in_h, wqkvT, b_qkv, qkv_buf, nullptr, NTOK, QKV_N, DMODEL);

    // 2) Flash attention (fp16 mma)
    cudaFuncSetAttribute(attn_h, cudaFuncAttributeMaxDynamicSharedMemorySize, ASMEM);
    attn_h<<<dim3(S_LEN / 64, BATCH * NHEADS), 128, ASMEM>>>(qkv_buf, att_buf);

    // 3) Output projection -> fp32 final out
    gemm_h<<<dim3(DMODEL / 128, NTOK / 128), 256, GSMEM>>>(
        att_buf, woutT, nullptr, nullptr, out, NTOK, DMODEL, DMODEL);
}

// round 9
// speedup vs baseline: 1.8678x; 1.0007x over previous
#include <cuda_runtime.h>
#include <cuda_fp16.h>
#include <stdint.h>

#define S_LEN   2048
#define BATCH   2
#define DMODEL  1024
#define NHEADS  16
#define DK      64
#define NTOK    (BATCH * S_LEN)      // 4096
#define QKV_N   (3 * DMODEL)         // 3072

// Scratch (allocation-free rule: __device__ globals)
__device__ __half g_in_h[(size_t)NTOK * DMODEL];     // input, fp16
__device__ __half g_wqkvT[(size_t)QKV_N * DMODEL];   // W_qkv^T fp16 [3072][1024]
__device__ __half g_woutT[(size_t)DMODEL * DMODEL];  // W_out^T fp16
__device__ __half g_qkv[(size_t)NTOK * QKV_N];       // qkv, fp16
__device__ __half g_att[(size_t)NTOK * DMODEL];      // attn out, fp16

// ---------------------------------------------------------------------------
__device__ __forceinline__ void mma16(float* c, const uint32_t* a, const uint32_t* b) {
    asm volatile(
        "mma.sync.aligned.m16n8k16.row.col.f32.f16.f16.f32 "
        "{%0,%1,%2,%3}, {%4,%5,%6,%7}, {%8,%9}, {%0,%1,%2,%3};"
        : "+f"(c[0]), "+f"(c[1]), "+f"(c[2]), "+f"(c[3])
        : "r"(a[0]), "r"(a[1]), "r"(a[2]), "r"(a[3]), "r"(b[0]), "r"(b[1]));
}
__device__ __forceinline__ void ldsm4(uint32_t* r, uint32_t addr) {
    asm volatile("ldmatrix.sync.aligned.m8n8.x4.shared.b16 {%0,%1,%2,%3}, [%4];"
                 : "=r"(r[0]), "=r"(r[1]), "=r"(r[2]), "=r"(r[3]) : "r"(addr));
}
__device__ __forceinline__ void ldsm4t(uint32_t* r, uint32_t addr) {
    asm volatile("ldmatrix.sync.aligned.m8n8.x4.trans.shared.b16 {%0,%1,%2,%3}, [%4];"
                 : "=r"(r[0]), "=r"(r[1]), "=r"(r[2]), "=r"(r[3]) : "r"(addr));
}
__device__ __forceinline__ void cp16(uint32_t saddr, const void* g) {
    asm volatile("cp.async.cg.shared.global [%0], [%1], 16;" :: "r"(saddr), "l"(g));
}
__device__ __forceinline__ void cp_commit() { asm volatile("cp.async.commit_group;"); }
__device__ __forceinline__ void cp_wait0()  { asm volatile("cp.async.wait_group 0;"); }
__device__ __forceinline__ float ex2f(float x) {
    float r; asm("ex2.approx.f32 %0, %1;" : "=f"(r) : "f"(x)); return r;
}

// ---------------------------------------------------------------------------
// Prep: f32 -> f16; transpose f32 -> f16
// ---------------------------------------------------------------------------
__global__ void tohalf_k(const float* __restrict__ in, __half* __restrict__ out, int n4) {
    int i = blockIdx.x * blockDim.x + threadIdx.x;
    if (i < n4) {
        float4 v = ((const float4*)in)[i];
        __half2 h0 = __floats2half2_rn(v.x, v.y);
        __half2 h1 = __floats2half2_rn(v.z, v.w);
        ((uint2*)out)[i] = make_uint2(*(uint32_t*)&h0, *(uint32_t*)&h1);
    }
}

// out[C][R] = half(in[R][C])
__global__ void transpose_h(const float* __restrict__ in, __half* __restrict__ out,
                            int R, int C) {
    __shared__ float t[32][33];
    int c0 = blockIdx.x * 32, r0 = blockIdx.y * 32;
    int x = threadIdx.x, y = threadIdx.y;
#pragma unroll
    for (int j = 0; j < 4; j++)
        t[y + 8 * j][x] = in[(size_t)(r0 + y + 8 * j) * C + c0 + x];
    __syncthreads();
#pragma unroll
    for (int j = 0; j < 4; j++)
        out[(size_t)(c0 + y + 8 * j) * R + r0 + x] = __float2half_rn(t[x][y + 8 * j]);
}

// ---------------------------------------------------------------------------
// FP16 GEMM (fp32 acc): C[M,N] = A[M,K] @ Bt[N,K]^T (+bias)
// 128x128 tile, BK=64 halves, 2-stage cp.async, ONE barrier per k-tile.
// 256 thr, warp 32x64. Stage = 2*128*72*2 = 36864 B; 2 stages = 73728 B.
// ---------------------------------------------------------------------------
#define GKS    72                       // smem stride in halves
#define GAB    (128 * GKS * 2)          // A tile bytes (18432)
#define GSTG_B (2 * GAB)                // stage bytes (36864)
#define GSMEM  (2 * GSTG_B)             // 73728

__global__ __launch_bounds__(256) void gemm_h(
    const __half* __restrict__ A, const __half* __restrict__ Bt,
    const float* __restrict__ bias, __half* __restrict__ Ch,
    float* __restrict__ Cf, int M, int N, int K)
{
    extern __shared__ char sg[];

    const int tid  = threadIdx.x;
    const int l    = tid & 31;
    const int wid  = tid >> 5;
    const int wm   = (wid & 3) * 32;
    const int wn   = (wid >> 2) * 64;
    const int g    = l >> 2;
    const int q    = l & 3;
    const int m0   = blockIdx.y * 128;
    const int n0   = blockIdx.x * 128;

    const uint32_t s0 = (uint32_t)__cvta_generic_to_shared(sg);

    float acc[2][8][4];
#pragma unroll
    for (int mt = 0; mt < 2; mt++)
#pragma unroll
        for (int nt = 0; nt < 8; nt++)
#pragma unroll
            for (int i = 0; i < 4; i++) acc[mt][nt][i] = 0.f;

    // ldmatrix per-lane byte offsets within a stage
    uint32_t aoff[2], boff[4];
#pragma unroll
    for (int mt = 0; mt < 2; mt++) {
        int row = wm + mt * 16 + ((l >> 3) & 1) * 8 + (l & 7);
        aoff[mt] = (uint32_t)(row * GKS + (l >> 4) * 8) * 2;
    }
#pragma unroll
    for (int j = 0; j < 4; j++) {
        int row = wn + 16 * j + (l & 7) + (l >> 4) * 8;
        boff[j] = GAB + (uint32_t)(row * GKS + ((l >> 3) & 1) * 8) * 2;
    }

    // cp.async coords: row = tid>>1, 64B half-row each, 4x16B chunks
    const int cr = tid >> 1;
    const int cb = (tid & 1) * 64;       // byte offset within 128B row
    auto prefetch = [&](int kt, int s) {
        const int k0 = kt * 64;          // halves
        const uint32_t sA = s0 + (uint32_t)s * GSTG_B;
        const uint32_t sB = sA + GAB;
        const __half* Ag = A  + (size_t)(m0 + cr) * K + k0 + (cb >> 1);
        const __half* Bg = Bt + (size_t)(n0 + cr) * K + k0 + (cb >> 1);
        uint32_t so = (uint32_t)(cr * GKS) * 2 + cb;
#pragma unroll
        for (int i = 0; i < 4; i++) {
            cp16(sA + so + i * 16, Ag + i * 8);
            cp16(sB + so + i * 16, Bg + i * 8);
        }
    };

    const int KT = K / 64;               // 16
    prefetch(0, 0); cp_commit();

    for (int kt = 0; kt < KT; kt++) {
        cp_wait0();
        __syncthreads();                 // also orders compute(kt-1) before overwrite
        if (kt + 1 < KT) { prefetch(kt + 1, (kt + 1) & 1); cp_commit(); }

        const uint32_t sb = s0 + (uint32_t)(kt & 1) * GSTG_B;
#pragma unroll
        for (int kk = 0; kk < 4; kk++) {      // 4 k16 steps
            uint32_t a[2][4], b[4][4];
#pragma unroll
            for (int mt = 0; mt < 2; mt++) ldsm4(a[mt], sb + aoff[mt] + kk * 32);
#pragma unroll
            for (int j = 0; j < 4; j++)   ldsm4(b[j], sb + boff[j] + kk * 32);
#pragma unroll
            for (int mt = 0; mt < 2; mt++)
#pragma unroll
                for (int nt = 0; nt < 8; nt++)
                    mma16(acc[mt][nt], a[mt], &b[nt >> 1][(nt & 1) * 2]);
        }
    }

#pragma unroll
    for (int mt = 0; mt < 2; mt++) {
#pragma unroll
        for (int nt = 0; nt < 8; nt++) {
            int row = m0 + wm + mt * 16 + g;
            int col = n0 + wn + nt * 8 + 2 * q;
            float b0 = bias ? bias[col] : 0.f;
            float b1 = bias ? bias[col + 1] : 0.f;
            float v00 = acc[mt][nt][0] + b0, v01 = acc[mt][nt][1] + b1;
            float v10 = acc[mt][nt][2] + b0, v11 = acc[mt][nt][3] + b1;
            if (Ch) {
                *(__half2*)(Ch + (size_t)row * N + col)       = __floats2half2_rn(v00, v01);
                *(__half2*)(Ch + (size_t)(row + 8) * N + col) = __floats2half2_rn(v10, v11);
            } else {
                *(float2*)(Cf + (size_t)row * N + col)       = make_float2(v00, v01);
                *(float2*)(Cf + (size_t)(row + 8) * N + col) = make_float2(v10, v11);
            }
        }
    }
}

// ---------------------------------------------------------------------------
// FP16 flash attention: q-tile 64, 128 thr = 4 warps x 16 rows.
// P kept in registers (QK acc frag layout == PV A frag layout) — no P smem.
// Smem halves (stride 72): Qs + Ks[2] + Vs[2] = 5*9216 = 46080 B.
// ---------------------------------------------------------------------------
#define AST 72                          // stride in halves
#define ATB (64 * AST * 2)              // one 64-row tile bytes (9216)
#define AQS_B 0
#define AKS_B ATB
#define AVS_B (AKS_B + 2 * ATB)
#define ASMEM (AVS_B + 2 * ATB)

__global__ __launch_bounds__(128) void attn_h(
    const __half* __restrict__ qkv, __half* __restrict__ out)
{
    extern __shared__ char sc[];
    const uint32_t s0 = (uint32_t)__cvta_generic_to_shared(sc);
    const uint32_t sQ = s0 + AQS_B;
    const uint32_t sK = s0 + AKS_B;
    const uint32_t sV = s0 + AVS_B;

    const int tid  = threadIdx.x;
    const int l    = tid & 31;
    const int wid  = tid >> 5;
    const int g    = l >> 2;
    const int q    = l & 3;
    const int wr   = wid * 16;
    const int bh   = blockIdx.y;
    const int b    = bh >> 4;
    const int h    = bh & 15;
    const int q0   = blockIdx.x * 64;

    const __half* Qg = qkv + (size_t)b * S_LEN * QKV_N + h * DK;
    const __half* Kg = Qg + DMODEL;
    const __half* Vg = Qg + 2 * DMODEL;

    // ldmatrix per-lane byte offsets
    const uint32_t afr = (uint32_t)((wr + ((l >> 3) & 1) * 8 + (l & 7)) * AST
                                    + (l >> 4) * 8) * 2;        // Q A-frag
    uint32_t koff[4], voff[4];
#pragma unroll
    for (int j = 0; j < 4; j++) {
        int krow = 16 * j + (l & 7) + (l >> 4) * 8;             // n = kv row
        koff[j] = (uint32_t)(krow * AST + ((l >> 3) & 1) * 8) * 2;
        int vrow = (l & 7) + ((l >> 3) & 1) * 8;                // k = kv row
        int vcol = 16 * j + (l >> 4) * 8;                       // n = d col
        voff[j] = (uint32_t)(vrow * AST + vcol) * 2;
    }

    const int lr = tid >> 3;
    const int lch = (tid & 7) * 8;
    auto load_tile = [&](uint32_t sdst, const __half* gsrc) {
#pragma unroll
        for (int i = 0; i < 4; i++) {
            int r = lr + i * 16;
            cp16(sdst + (uint32_t)(r * AST + lch) * 2, gsrc + (size_t)r * QKV_N + lch);
        }
    };

    load_tile(sQ, Qg + (size_t)q0 * QKV_N);
    load_tile(sK, Kg);
    load_tile(sV, Vg);
    cp_commit();

    const float C = 0.18033688011f;      // 0.125 * log2(e)
    float m_i[2] = {-1e30f, -1e30f};
    float l_i[2] = {0.f, 0.f};
    float o[8][4];
#pragma unroll
    for (int nt = 0; nt < 8; nt++)
#pragma unroll
        for (int i = 0; i < 4; i++) o[nt][i] = 0.f;

    const int NT = S_LEN / 64;
    for (int kt = 0; kt < NT; kt++) {
        cp_wait0();
        __syncthreads();
        if (kt + 1 < NT) {
            uint32_t buf = (uint32_t)((kt + 1) & 1) * ATB;
            load_tile(sK + buf, Kg + (size_t)(kt + 1) * 64 * QKV_N);
            load_tile(sV + buf, Vg + (size_t)(kt + 1) * 64 * QKV_N);
            cp_commit();
        }
        const uint32_t sKb = sK + (uint32_t)(kt & 1) * ATB;
        const uint32_t sVb = sV + (uint32_t)(kt & 1) * ATB;

        // ---- S = Q K^T ----
        float sacc[8][4];
#pragma unroll
        for (int nt = 0; nt < 8; nt++)
#pragma unroll
            for (int i = 0; i < 4; i++) sacc[nt][i] = 0.f;

#pragma unroll
        for (int kk = 0; kk < 4; kk++) {
            uint32_t a[4], kb[4][4];
            ldsm4(a, sQ + afr + kk * 32);
#pragma unroll
            for (int j = 0; j < 4; j++) ldsm4(kb[j], sKb + koff[j] + kk * 32);
#pragma unroll
            for (int nt = 0; nt < 8; nt++)
                mma16(sacc[nt], a, &kb[nt >> 1][(nt & 1) * 2]);
        }

        // ---- online softmax; P packed straight into PV A-fragments ----
        uint32_t pfrag[8][2];
#pragma unroll
        for (int rh = 0; rh < 2; rh++) {
            float rm = -1e30f;
#pragma unroll
            for (int nt = 0; nt < 8; nt++)
                rm = fmaxf(rm, fmaxf(sacc[nt][2 * rh], sacc[nt][2 * rh + 1]));
            rm = fmaxf(rm, __shfl_xor_sync(0xffffffffu, rm, 1));
            rm = fmaxf(rm, __shfl_xor_sync(0xffffffffu, rm, 2));

            float mnew = fmaxf(m_i[rh], rm);
            float mC = mnew * C;
            float corr = ex2f(m_i[rh] * C - mC);
            m_i[rh] = mnew;

            float rs = 0.f;
#pragma unroll
            for (int nt = 0; nt < 8; nt++) {
                float p0 = ex2f(fmaf(sacc[nt][2 * rh], C, -mC));
                float p1 = ex2f(fmaf(sacc[nt][2 * rh + 1], C, -mC));
                __half2 ph = __floats2half2_rn(p0, p1);
                pfrag[nt][rh] = *(uint32_t*)&ph;
                rs += p0 + p1;
            }
            rs += __shfl_xor_sync(0xffffffffu, rs, 1);
            rs += __shfl_xor_sync(0xffffffffu, rs, 2);
            l_i[rh] = l_i[rh] * corr + rs;
#pragma unroll
            for (int nt = 0; nt < 8; nt++) {
                o[nt][2 * rh]     *= corr;
                o[nt][2 * rh + 1] *= corr;
            }
        }

        // ---- O += P V (P in regs; V via ldmatrix.trans) ----
#pragma unroll
        for (int kk = 0; kk < 4; kk++) {
            uint32_t a[4] = {pfrag[2 * kk][0], pfrag[2 * kk][1],
                             pfrag[2 * kk + 1][0], pfrag[2 * kk + 1][1]};
            uint32_t vb[4][4];
            const uint32_t vkk = sVb + (uint32_t)(kk * 16 * AST) * 2;
#pragma unroll
            for (int j = 0; j < 4; j++) ldsm4t(vb[j], vkk + voff[j]);
#pragma unroll
            for (int nt = 0; nt < 8; nt++)
                mma16(o[nt], a, &vb[nt >> 1][(nt & 1) * 2]);
        }
    }

    // ---- normalize + write fp16 ----
#pragma unroll
    for (int rh = 0; rh < 2; rh++) {
        float inv = 1.f / l_i[rh];
        int token = b * S_LEN + q0 + wr + g + 8 * rh;
        __half* op = out + (size_t)token * DMODEL + h * DK;
#pragma unroll
        for (int nt = 0; nt < 8; nt++)
            *(__half2*)(op + nt * 8 + 2 * q) =
                __floats2half2_rn(o[nt][2 * rh] * inv, o[nt][2 * rh + 1] * inv);
    }
}

// ---------------------------------------------------------------------------
extern "C" void kernel_launch(void* const* d_in, const int* in_sizes, int n_in,
                              void* d_out, int out_size)
{
    const float* input = (const float*)d_in[0];
    const float* W_qkv = (const float*)d_in[1];
    const float* b_qkv = (const float*)d_in[2];
    const float* W_out = (const float*)d_in[3];
    float* out = (float*)d_out;

    __half *in_h, *wqkvT, *woutT, *qkv_buf, *att_buf;
    cudaGetSymbolAddress((void**)&in_h,    g_in_h);
    cudaGetSymbolAddress((void**)&wqkvT,   g_wqkvT);
    cudaGetSymbolAddress((void**)&woutT,   g_woutT);
    cudaGetSymbolAddress((void**)&qkv_buf, g_qkv);
    cudaGetSymbolAddress((void**)&att_buf, g_att);

    // 0) input -> fp16; weights -> fp16 transposed (k-major B operands)
    {
        int n1 = NTOK * DMODEL / 4;
        tohalf_k<<<(n1 + 255) / 256, 256>>>(input, in_h, n1);
        transpose_h<<<dim3(QKV_N / 32, DMODEL / 32), dim3(32, 8)>>>(
            W_qkv, wqkvT, DMODEL, QKV_N);
        transpose_h<<<dim3(DMODEL / 32, DMODEL / 32), dim3(32, 8)>>>(
            W_out, woutT, DMODEL, DMODEL);
    }

    cudaFuncSetAttribute(gemm_h, cudaFuncAttributeMaxDynamicSharedMemorySize, GSMEM);

    // 1) QKV projection + bias -> fp16 qkv
    gemm_h<<<dim3(QKV_N / 128, NTOK / 128), 256, GSMEM>>>(
        in_h, wqkvT, b_qkv, qkv_buf, nullptr, NTOK, QKV_N, DMODEL);

    // 2) Flash attention (fp16 mma, register-resident P)
    cudaFuncSetAttribute(attn_h, cudaFuncAttributeMaxDynamicSharedMemorySize, ASMEM);
    attn_h<<<dim3(S_LEN / 64, BATCH * NHEADS), 128, ASMEM>>>(qkv_buf, att_buf);

    // 3) Output projection -> fp32 final out
    gemm_h<<<dim3(DMODEL / 128, NTOK / 128), 256, GSMEM>>>(
        att_buf, woutT, nullptr, nullptr, out, NTOK, DMODEL, DMODEL);
}

// round 10
// speedup vs baseline: 2.0858x; 1.1167x over previous
#include <cuda_runtime.h>
#include <cuda_fp16.h>
#include <stdint.h>

#define S_LEN   2048
#define BATCH   2
#define DMODEL  1024
#define NHEADS  16
#define DK      64
#define NTOK    (BATCH * S_LEN)      // 4096
#define QKV_N   (3 * DMODEL)         // 3072

// Scratch (allocation-free rule: __device__ globals)
__device__ __half g_in_h[(size_t)NTOK * DMODEL];     // input, fp16
__device__ __half g_wqkvT[(size_t)QKV_N * DMODEL];   // W_qkv^T fp16 [3072][1024]
__device__ __half g_woutT[(size_t)DMODEL * DMODEL];  // W_out^T fp16
__device__ __half g_qkv[(size_t)NTOK * QKV_N];       // qkv, fp16
__device__ __half g_att[(size_t)NTOK * DMODEL];      // attn out, fp16

// ---------------------------------------------------------------------------
__device__ __forceinline__ void mma16(float* c, const uint32_t* a, const uint32_t* b) {
    asm volatile(
        "mma.sync.aligned.m16n8k16.row.col.f32.f16.f16.f32 "
        "{%0,%1,%2,%3}, {%4,%5,%6,%7}, {%8,%9}, {%0,%1,%2,%3};"
        : "+f"(c[0]), "+f"(c[1]), "+f"(c[2]), "+f"(c[3])
        : "r"(a[0]), "r"(a[1]), "r"(a[2]), "r"(a[3]), "r"(b[0]), "r"(b[1]));
}
__device__ __forceinline__ void ldsm4(uint32_t* r, uint32_t addr) {
    asm volatile("ldmatrix.sync.aligned.m8n8.x4.shared.b16 {%0,%1,%2,%3}, [%4];"
                 : "=r"(r[0]), "=r"(r[1]), "=r"(r[2]), "=r"(r[3]) : "r"(addr));
}
__device__ __forceinline__ void ldsm4t(uint32_t* r, uint32_t addr) {
    asm volatile("ldmatrix.sync.aligned.m8n8.x4.trans.shared.b16 {%0,%1,%2,%3}, [%4];"
                 : "=r"(r[0]), "=r"(r[1]), "=r"(r[2]), "=r"(r[3]) : "r"(addr));
}
__device__ __forceinline__ void cp16(uint32_t saddr, const void* g) {
    asm volatile("cp.async.cg.shared.global [%0], [%1], 16;" :: "r"(saddr), "l"(g));
}
__device__ __forceinline__ void cp_commit() { asm volatile("cp.async.commit_group;"); }
__device__ __forceinline__ void cp_wait0()  { asm volatile("cp.async.wait_group 0;"); }
__device__ __forceinline__ void cp_wait2()  { asm volatile("cp.async.wait_group 2;"); }
__device__ __forceinline__ float ex2f(float x) {
    float r; asm("ex2.approx.f32 %0, %1;" : "=f"(r) : "f"(x)); return r;
}

// ---------------------------------------------------------------------------
// Prep: f32 -> f16; transpose f32 -> f16
// ---------------------------------------------------------------------------
__global__ void tohalf_k(const float* __restrict__ in, __half* __restrict__ out, int n4) {
    int i = blockIdx.x * blockDim.x + threadIdx.x;
    if (i < n4) {
        float4 v = ((const float4*)in)[i];
        __half2 h0 = __floats2half2_rn(v.x, v.y);
        __half2 h1 = __floats2half2_rn(v.z, v.w);
        ((uint2*)out)[i] = make_uint2(*(uint32_t*)&h0, *(uint32_t*)&h1);
    }
}

// out[C][R] = half(in[R][C])
__global__ void transpose_h(const float* __restrict__ in, __half* __restrict__ out,
                            int R, int C) {
    __shared__ float t[32][33];
    int c0 = blockIdx.x * 32, r0 = blockIdx.y * 32;
    int x = threadIdx.x, y = threadIdx.y;
#pragma unroll
    for (int j = 0; j < 4; j++)
        t[y + 8 * j][x] = in[(size_t)(r0 + y + 8 * j) * C + c0 + x];
    __syncthreads();
#pragma unroll
    for (int j = 0; j < 4; j++)
        out[(size_t)(c0 + y + 8 * j) * R + r0 + x] = __float2half_rn(t[x][y + 8 * j]);
}

// ---------------------------------------------------------------------------
// FP16 GEMM (fp32 acc): C[M,N] = A[M,K] @ Bt[N,K]^T (+bias)
// 128x128 tile, BK=32 halves, 4-stage cp.async (wait_group 2, always-commit),
// fragment double-buffering across the 2 k16 steps. 256 thr, warp 32x64.
// Stage = 2*128*40*2 = 20480 B; 4 stages = 81920 B -> 2 CTA/SM.
// ---------------------------------------------------------------------------
#define GKS    40                       // smem stride in halves
#define GAB    (128 * GKS * 2)          // A tile bytes (10240)
#define GSTG_B (2 * GAB)                // stage bytes (20480)
#define GSMEM  (4 * GSTG_B)             // 81920

__global__ __launch_bounds__(256, 2) void gemm_h(
    const __half* __restrict__ A, const __half* __restrict__ Bt,
    const float* __restrict__ bias, __half* __restrict__ Ch,
    float* __restrict__ Cf, int M, int N, int K)
{
    extern __shared__ char sg[];

    const int tid  = threadIdx.x;
    const int l    = tid & 31;
    const int wid  = tid >> 5;
    const int wm   = (wid & 3) * 32;
    const int wn   = (wid >> 2) * 64;
    const int g    = l >> 2;
    const int q    = l & 3;
    const int m0   = blockIdx.y * 128;
    const int n0   = blockIdx.x * 128;

    const uint32_t s0 = (uint32_t)__cvta_generic_to_shared(sg);

    float acc[2][8][4];
#pragma unroll
    for (int mt = 0; mt < 2; mt++)
#pragma unroll
        for (int nt = 0; nt < 8; nt++)
#pragma unroll
            for (int i = 0; i < 4; i++) acc[mt][nt][i] = 0.f;

    // ldmatrix per-lane byte offsets within a stage
    uint32_t aoff[2], boff[4];
#pragma unroll
    for (int mt = 0; mt < 2; mt++) {
        int row = wm + mt * 16 + ((l >> 3) & 1) * 8 + (l & 7);
        aoff[mt] = (uint32_t)(row * GKS + (l >> 4) * 8) * 2;
    }
#pragma unroll
    for (int j = 0; j < 4; j++) {
        int row = wn + 16 * j + (l & 7) + (l >> 4) * 8;
        boff[j] = GAB + (uint32_t)(row * GKS + ((l >> 3) & 1) * 8) * 2;
    }

    // cp.async coords: 2x16B chunks per thread per matrix
    const int cr = tid >> 1;              // row 0..127
    const int cb = (tid & 1) * 32;        // byte col {0,32}
    auto prefetch = [&](int kt, int s) {
        const int k0 = kt * 32;           // halves
        const uint32_t sA = s0 + (uint32_t)s * GSTG_B;
        const uint32_t sB = sA + GAB;
        const __half* Ag = A  + (size_t)(m0 + cr) * K + k0 + (cb >> 1);
        const __half* Bg = Bt + (size_t)(n0 + cr) * K + k0 + (cb >> 1);
        uint32_t so = (uint32_t)(cr * GKS) * 2 + cb;
        cp16(sA + so,      Ag);
        cp16(sA + so + 16, Ag + 8);
        cp16(sB + so,      Bg);
        cp16(sB + so + 16, Bg + 8);
    };

    const int KT = K / 32;
    prefetch(0, 0); cp_commit();
    prefetch(1, 1); cp_commit();
    prefetch(2, 2); cp_commit();

    for (int kt = 0; kt < KT; kt++) {
        cp_wait2();                      // tile kt has exactly 2 newer groups
        __syncthreads();
        if (kt + 3 < KT) prefetch(kt + 3, (kt + 3) & 3);
        cp_commit();                     // ALWAYS commit (empty groups keep count exact)

        const uint32_t sb = s0 + (uint32_t)(kt & 3) * GSTG_B;
        uint32_t a[2][2][4], b[2][4][4];
#pragma unroll
        for (int mt = 0; mt < 2; mt++) ldsm4(a[0][mt], sb + aoff[mt]);
#pragma unroll
        for (int j = 0; j < 4; j++)    ldsm4(b[0][j], sb + boff[j]);

#pragma unroll
        for (int kk = 0; kk < 2; kk++) {
            if (kk == 0) {               // prefetch kk=1 frags during kk=0 mma
#pragma unroll
                for (int mt = 0; mt < 2; mt++) ldsm4(a[1][mt], sb + aoff[mt] + 32);
#pragma unroll
                for (int j = 0; j < 4; j++)    ldsm4(b[1][j], sb + boff[j] + 32);
            }
#pragma unroll
            for (int mt = 0; mt < 2; mt++)
#pragma unroll
                for (int nt = 0; nt < 8; nt++)
                    mma16(acc[mt][nt], a[kk][mt], &b[kk][nt >> 1][(nt & 1) * 2]);
        }
    }

#pragma unroll
    for (int mt = 0; mt < 2; mt++) {
#pragma unroll
        for (int nt = 0; nt < 8; nt++) {
            int row = m0 + wm + mt * 16 + g;
            int col = n0 + wn + nt * 8 + 2 * q;
            float b0 = bias ? bias[col] : 0.f;
            float b1 = bias ? bias[col + 1] : 0.f;
            float v00 = acc[mt][nt][0] + b0, v01 = acc[mt][nt][1] + b1;
            float v10 = acc[mt][nt][2] + b0, v11 = acc[mt][nt][3] + b1;
            if (Ch) {
                *(__half2*)(Ch + (size_t)row * N + col)       = __floats2half2_rn(v00, v01);
                *(__half2*)(Ch + (size_t)(row + 8) * N + col) = __floats2half2_rn(v10, v11);
            } else {
                *(float2*)(Cf + (size_t)row * N + col)       = make_float2(v00, v01);
                *(float2*)(Cf + (size_t)(row + 8) * N + col) = make_float2(v10, v11);
            }
        }
    }
}

// ---------------------------------------------------------------------------
// FP16 flash attention: q-tile 64, 128 thr = 4 warps x 16 rows.
// Q fragments hoisted out of the kv loop (loaded once); P stays in registers.
// Smem halves (stride 72): Qs + Ks[2] + Vs[2] = 5*9216 = 46080 B -> 4 CTA/SM.
// ---------------------------------------------------------------------------
#define AST 72                          // stride in halves
#define ATB (64 * AST * 2)              // one 64-row tile bytes (9216)
#define AQS_B 0
#define AKS_B ATB
#define AVS_B (AKS_B + 2 * ATB)
#define ASMEM (AVS_B + 2 * ATB)

__global__ __launch_bounds__(128, 4) void attn_h(
    const __half* __restrict__ qkv, __half* __restrict__ out)
{
    extern __shared__ char sc[];
    const uint32_t s0 = (uint32_t)__cvta_generic_to_shared(sc);
    const uint32_t sQ = s0 + AQS_B;
    const uint32_t sK = s0 + AKS_B;
    const uint32_t sV = s0 + AVS_B;

    const int tid  = threadIdx.x;
    const int l    = tid & 31;
    const int wid  = tid >> 5;
    const int g    = l >> 2;
    const int q    = l & 3;
    const int wr   = wid * 16;
    const int bh   = blockIdx.y;
    const int b    = bh >> 4;
    const int h    = bh & 15;
    const int q0   = blockIdx.x * 64;

    const __half* Qg = qkv + (size_t)b * S_LEN * QKV_N + h * DK;
    const __half* Kg = Qg + DMODEL;
    const __half* Vg = Qg + 2 * DMODEL;

    // ldmatrix per-lane byte offsets
    const uint32_t afr = (uint32_t)((wr + ((l >> 3) & 1) * 8 + (l & 7)) * AST
                                    + (l >> 4) * 8) * 2;        // Q A-frag
    uint32_t koff[4], voff[4];
#pragma unroll
    for (int j = 0; j < 4; j++) {
        int krow = 16 * j + (l & 7) + (l >> 4) * 8;             // n = kv row
        koff[j] = (uint32_t)(krow * AST + ((l >> 3) & 1) * 8) * 2;
        int vrow = (l & 7) + ((l >> 3) & 1) * 8;                // k = kv row
        int vcol = 16 * j + (l >> 4) * 8;                       // n = d col
        voff[j] = (uint32_t)(vrow * AST + vcol) * 2;
    }

    const int lr = tid >> 3;
    const int lch = (tid & 7) * 8;
    auto load_tile = [&](uint32_t sdst, const __half* gsrc) {
#pragma unroll
        for (int i = 0; i < 4; i++) {
            int r = lr + i * 16;
            cp16(sdst + (uint32_t)(r * AST + lch) * 2, gsrc + (size_t)r * QKV_N + lch);
        }
    };

    load_tile(sQ, Qg + (size_t)q0 * QKV_N);
    load_tile(sK, Kg);
    load_tile(sV, Vg);
    cp_commit();

    const float C = 0.18033688011f;      // 0.125 * log2(e)
    float m_i[2] = {-1e30f, -1e30f};
    float l_i[2] = {0.f, 0.f};
    float o[8][4];
#pragma unroll
    for (int nt = 0; nt < 8; nt++)
#pragma unroll
        for (int i = 0; i < 4; i++) o[nt][i] = 0.f;

    uint32_t qf[4][4];                    // hoisted Q fragments (16 regs)

    const int NT = S_LEN / 64;
    for (int kt = 0; kt < NT; kt++) {
        cp_wait0();
        __syncthreads();
        if (kt == 0) {                   // Q resident now; load frags once
#pragma unroll
            for (int kk = 0; kk < 4; kk++) ldsm4(qf[kk], sQ + afr + kk * 32);
        }
        if (kt + 1 < NT) {
            uint32_t buf = (uint32_t)((kt + 1) & 1) * ATB;
            load_tile(sK + buf, Kg + (size_t)(kt + 1) * 64 * QKV_N);
            load_tile(sV + buf, Vg + (size_t)(kt + 1) * 64 * QKV_N);
            cp_commit();
        }
        const uint32_t sKb = sK + (uint32_t)(kt & 1) * ATB;
        const uint32_t sVb = sV + (uint32_t)(kt & 1) * ATB;

        // ---- S = Q K^T ----
        float sacc[8][4];
#pragma unroll
        for (int nt = 0; nt < 8; nt++)
#pragma unroll
            for (int i = 0; i < 4; i++) sacc[nt][i] = 0.f;

#pragma unroll
        for (int kk = 0; kk < 4; kk++) {
            uint32_t kb[4][4];
#pragma unroll
            for (int j = 0; j < 4; j++) ldsm4(kb[j], sKb + koff[j] + kk * 32);
#pragma unroll
            for (int nt = 0; nt < 8; nt++)
                mma16(sacc[nt], qf[kk], &kb[nt >> 1][(nt & 1) * 2]);
        }

        // ---- online softmax; P packed straight into PV A-fragments ----
        uint32_t pfrag[8][2];
#pragma unroll
        for (int rh = 0; rh < 2; rh++) {
            float rm = -1e30f;
#pragma unroll
            for (int nt = 0; nt < 8; nt++)
                rm = fmaxf(rm, fmaxf(sacc[nt][2 * rh], sacc[nt][2 * rh + 1]));
            rm = fmaxf(rm, __shfl_xor_sync(0xffffffffu, rm, 1));
            rm = fmaxf(rm, __shfl_xor_sync(0xffffffffu, rm, 2));

            float mnew = fmaxf(m_i[rh], rm);
            float mC = mnew * C;
            float corr = ex2f(m_i[rh] * C - mC);
            m_i[rh] = mnew;

            float rs = 0.f;
#pragma unroll
            for (int nt = 0; nt < 8; nt++) {
                float p0 = ex2f(fmaf(sacc[nt][2 * rh], C, -mC));
                float p1 = ex2f(fmaf(sacc[nt][2 * rh + 1], C, -mC));
                __half2 ph = __floats2half2_rn(p0, p1);
                pfrag[nt][rh] = *(uint32_t*)&ph;
                rs += p0 + p1;
            }
            rs += __shfl_xor_sync(0xffffffffu, rs, 1);
            rs += __shfl_xor_sync(0xffffffffu, rs, 2);
            l_i[rh] = l_i[rh] * corr + rs;
#pragma unroll
            for (int nt = 0; nt < 8; nt++) {
                o[nt][2 * rh]     *= corr;
                o[nt][2 * rh + 1] *= corr;
            }
        }

        // ---- O += P V (P in regs; V via ldmatrix.trans) ----
#pragma unroll
        for (int kk = 0; kk < 4; kk++) {
            uint32_t a[4] = {pfrag[2 * kk][0], pfrag[2 * kk][1],
                             pfrag[2 * kk + 1][0], pfrag[2 * kk + 1][1]};
            uint32_t vb[4][4];
            const uint32_t vkk = sVb + (uint32_t)(kk * 16 * AST) * 2;
#pragma unroll
            for (int j = 0; j < 4; j++) ldsm4t(vb[j], vkk + voff[j]);
#pragma unroll
            for (int nt = 0; nt < 8; nt++)
                mma16(o[nt], a, &vb[nt >> 1][(nt & 1) * 2]);
        }
    }

    // ---- normalize + write fp16 ----
#pragma unroll
    for (int rh = 0; rh < 2; rh++) {
        float inv = 1.f / l_i[rh];
        int token = b * S_LEN + q0 + wr + g + 8 * rh;
        __half* op = out + (size_t)token * DMODEL + h * DK;
#pragma unroll
        for (int nt = 0; nt < 8; nt++)
            *(__half2*)(op + nt * 8 + 2 * q) =
                __floats2half2_rn(o[nt][2 * rh] * inv, o[nt][2 * rh + 1] * inv);
    }
}

// ---------------------------------------------------------------------------
extern "C" void kernel_launch(void* const* d_in, const int* in_sizes, int n_in,
                              void* d_out, int out_size)
{
    const float* input = (const float*)d_in[0];
    const float* W_qkv = (const float*)d_in[1];
    const float* b_qkv = (const float*)d_in[2];
    const float* W_out = (const float*)d_in[3];
    float* out = (float*)d_out;

    __half *in_h, *wqkvT, *woutT, *qkv_buf, *att_buf;
    cudaGetSymbolAddress((void**)&in_h,    g_in_h);
    cudaGetSymbolAddress((void**)&wqkvT,   g_wqkvT);
    cudaGetSymbolAddress((void**)&woutT,   g_woutT);
    cudaGetSymbolAddress((void**)&qkv_buf, g_qkv);
    cudaGetSymbolAddress((void**)&att_buf, g_att);

    // 0) input -> fp16; weights -> fp16 transposed (k-major B operands)
    {
        int n1 = NTOK * DMODEL / 4;
        tohalf_k<<<(n1 + 255) / 256, 256>>>(input, in_h, n1);
        transpose_h<<<dim3(QKV_N / 32, DMODEL / 32), dim3(32, 8)>>>(
            W_qkv, wqkvT, DMODEL, QKV_N);
        transpose_h<<<dim3(DMODEL / 32, DMODEL / 32), dim3(32, 8)>>>(
            W_out, woutT, DMODEL, DMODEL);
    }

    cudaFuncSetAttribute(gemm_h, cudaFuncAttributeMaxDynamicSharedMemorySize, GSMEM);

    // 1) QKV projection + bias -> fp16 qkv
    gemm_h<<<dim3(QKV_N / 128, NTOK / 128), 256, GSMEM>>>(
        in_h, wqkvT, b_qkv, qkv_buf, nullptr, NTOK, QKV_N, DMODEL);

    // 2) Flash attention (fp16 mma, register P, hoisted Q frags)
    cudaFuncSetAttribute(attn_h, cudaFuncAttributeMaxDynamicSharedMemorySize, ASMEM);
    attn_h<<<dim3(S_LEN / 64, BATCH * NHEADS), 128, ASMEM>>>(qkv_buf, att_buf);

    // 3) Output projection -> fp32 final out
    gemm_h<<<dim3(DMODEL / 128, NTOK / 128), 256, GSMEM>>>(
        att_buf, woutT, nullptr, nullptr, out, NTOK, DMODEL, DMODEL);
}